// round 1
// baseline (speedup 1.0000x reference)
#include <cuda_runtime.h>
#include <cuda_bf16.h>

#define KEHALF  7.199822675975274f
#define CUTOFF  10.0f
#define L2E     1.4426950408889634f

// Per-atom packed record: {Z, z = Z^softplus(apow), idx_m as int bits, pad}
__device__ float4 g_atom[131072];

__device__ __forceinline__ float softplus_f(float x) {
    // log(1 + exp(x)), safe for the small positive values seen here
    return (x > 20.0f) ? x : log1pf(__expf(x));
}

__global__ void k_atom_prep(const float* __restrict__ Z,
                            const int*   __restrict__ idx_m,
                            const float* __restrict__ apow,
                            int N,
                            float* __restrict__ y, int M) {
    int i = blockIdx.x * blockDim.x + threadIdx.x;
    if (i < M) y[i] = 0.0f;               // zero output (poisoned by harness)
    if (i >= N || i >= 131072) return;
    float sp = softplus_f(apow[0]);
    float Zi = Z[i];
    float z  = exp2f(sp * log2f(Zi));     // Z >= 1, so log2f is safe
    g_atom[i] = make_float4(Zi, z, __int_as_float(idx_m[i]), 0.0f);
}

__global__ void __launch_bounds__(256)
k_edge_energy(const float* __restrict__ r,
              const int*   __restrict__ ii,
              const int*   __restrict__ jj,
              const float* __restrict__ adiv,
              const float* __restrict__ av,
              const float* __restrict__ cv,
              int E,
              float* __restrict__ y, int M) {
    extern __shared__ float bins[];
    for (int b = threadIdx.x; b < M; b += blockDim.x) bins[b] = 0.0f;

    // Per-thread scalar prep (all L1-cached tiny loads; once per thread)
    float sp_adiv = softplus_f(adiv[0]);
    float a0 = softplus_f(av[0]), a1 = softplus_f(av[1]);
    float a2 = softplus_f(av[2]), a3 = softplus_f(av[3]);
    float c0 = softplus_f(cv[0]), c1 = softplus_f(cv[1]);
    float c2 = softplus_f(cv[2]), c3 = softplus_f(cv[3]);
    float cinv = 1.0f / (fabsf(c0) + fabsf(c1) + fabsf(c2) + fabsf(c3));
    c0 *= cinv; c1 *= cinv; c2 *= cinv; c3 *= cinv;
    // fold sp_adiv and log2(e) into the exponent coefficients:
    //   exp(-a_k * (z_i+z_j)*sp_adiv * d) = exp2(-b_k * (z_i+z_j) * d)
    float b0 = a0 * sp_adiv * L2E, b1 = a1 * sp_adiv * L2E;
    float b2 = a2 * sp_adiv * L2E, b3 = a3 * sp_adiv * L2E;

    __syncthreads();

    int stride = gridDim.x * blockDim.x;
    for (int e = blockIdx.x * blockDim.x + threadIdx.x; e < E; e += stride) {
        float rx = r[3 * e + 0];
        float ry = r[3 * e + 1];
        float rz = r[3 * e + 2];
        int i = ii[e];
        int j = jj[e];
        float4 ai = g_atom[i];   // {Z_i, z_i, m_i, -}
        float4 aj = g_atom[j];   // {Z_j, z_j, -,   -}

        float s  = fmaf(rx, rx, fmaf(ry, ry, rz * rz));
        float rs = rsqrtf(s);    // 1/d
        float d  = s * rs;       // d

        float t = (ai.y + aj.y) * d;
        float f = c0 * exp2f(-b0 * t)
                + c1 * exp2f(-b1 * t)
                + c2 * exp2f(-b2 * t)
                + c3 * exp2f(-b3 * t);

        // PhysNet cutoff: 1 - 6u^5 + 15u^4 - 10u^3 = 1 + u^3*(-10 + 15u - 6u^2)
        float u  = d * (1.0f / CUTOFF);
        float u3 = u * u * u;
        float q  = fmaf(-6.0f, u, 15.0f);
        q        = fmaf(q, u, -10.0f);
        float fc = fmaf(u3, q, 1.0f);
        if (d >= CUTOFF) fc = 0.0f;

        float ee = KEHALF * f * fc * ai.x * aj.x * rs;

        // The vast majority of edges underflow to exactly 0 (a*d huge).
        // Skipping them collapses the smem-atomic cost.
        if (ee != 0.0f) {
            int m = __float_as_int(ai.z);
            atomicAdd(&bins[m], ee);
        }
    }

    __syncthreads();
    for (int b = threadIdx.x; b < M; b += blockDim.x) {
        float v = bins[b];
        if (v != 0.0f) atomicAdd(&y[b], v);
    }
}

extern "C" void kernel_launch(void* const* d_in, const int* in_sizes, int n_in,
                              void* d_out, int out_size) {
    const float* Z    = (const float*)d_in[0];
    const float* r    = (const float*)d_in[1];
    const int*   ii   = (const int*)  d_in[2];
    const int*   jj   = (const int*)  d_in[3];
    const int*   im   = (const int*)  d_in[4];
    const float* adiv = (const float*)d_in[5];
    const float* apow = (const float*)d_in[6];
    const float* av   = (const float*)d_in[7];
    const float* cv   = (const float*)d_in[8];

    int N = in_sizes[0];
    int E = in_sizes[2];
    int M = out_size;
    float* y = (float*)d_out;

    int prep_n = (N > M ? N : M);
    k_atom_prep<<<(prep_n + 255) / 256, 256>>>(Z, im, apow, N, y, M);

    int grid = 888;  // 148 SMs * 6 CTAs
    size_t smem = (size_t)M * sizeof(float);
    k_edge_energy<<<grid, 256, smem>>>(r, ii, jj, adiv, av, cv, E, y, M);
}

// round 2
// speedup vs baseline: 1.0385x; 1.0385x over previous
#include <cuda_runtime.h>
#include <cuda_bf16.h>

#define KEHALF  7.199822675975274f
#define CUTOFF  10.0f
#define L2E     1.4426950408889634f

// Per-atom packed record: {z = Z^softplus(apow), int bits: (Zint<<10)|m}
__device__ float2 g_atom2[131072];

__device__ __forceinline__ float softplus_f(float x) {
    return (x > 20.0f) ? x : log1pf(__expf(x));
}

__global__ void k_atom_prep(const float* __restrict__ Z,
                            const int*   __restrict__ idx_m,
                            const float* __restrict__ apow,
                            int N,
                            float* __restrict__ y, int M) {
    int i = blockIdx.x * blockDim.x + threadIdx.x;
    if (i < M) y[i] = 0.0f;
    if (i >= N || i >= 131072) return;
    float sp = softplus_f(apow[0]);
    float Zi = Z[i];
    float z  = exp2f(sp * log2f(Zi));          // Z >= 1
    int   zi = (int)(Zi + 0.5f);               // exact small integer
    int   pk = (zi << 10) | (idx_m[i] & 1023);
    g_atom2[i] = make_float2(z, __int_as_float(pk));
}

__device__ __forceinline__ float edge_energy(
    float rx, float ry, float rz, float2 ai, float2 aj,
    float b0, float b1, float b2, float b3,
    float c0, float c1, float c2, float c3,
    float thr, int* m_out)
{
    float s  = fmaf(rx, rx, fmaf(ry, ry, rz * rz));
    float rs = rsqrtf(s);        // 1/d
    float d  = s * rs;           // d

    float t  = (ai.x + aj.x) * d;
    int   pi = __float_as_int(ai.y);
    int   pj = __float_as_int(aj.y);
    *m_out   = pi & 1023;

    float ee = 0.0f;
    // All four exp2 terms underflow to exactly 0 when b_min*t >= 151
    // (2^-151 < smallest denormal). Reference also produces exact 0 there.
    if (t < thr && d < CUTOFF) {
        float f = c0 * exp2f(-b0 * t)
                + c1 * exp2f(-b1 * t)
                + c2 * exp2f(-b2 * t)
                + c3 * exp2f(-b3 * t);
        float u  = d * (1.0f / CUTOFF);
        float u3 = u * u * u;
        float q  = fmaf(-6.0f, u, 15.0f);
        q        = fmaf(q, u, -10.0f);
        float fc = fmaf(u3, q, 1.0f);
        float Zi = (float)(pi >> 10);
        float Zj = (float)(pj >> 10);
        ee = KEHALF * f * fc * Zi * Zj * rs;
    }
    return ee;
}

__global__ void __launch_bounds__(256)
k_edge_energy(const float* __restrict__ r,
              const int*   __restrict__ ii,
              const int*   __restrict__ jj,
              const float* __restrict__ adiv,
              const float* __restrict__ av,
              const float* __restrict__ cv,
              int E,
              float* __restrict__ y, int M) {
    extern __shared__ float bins[];
    for (int b = threadIdx.x; b < M; b += blockDim.x) bins[b] = 0.0f;

    float sp_adiv = softplus_f(adiv[0]);
    float a0 = softplus_f(av[0]), a1 = softplus_f(av[1]);
    float a2 = softplus_f(av[2]), a3 = softplus_f(av[3]);
    float c0 = softplus_f(cv[0]), c1 = softplus_f(cv[1]);
    float c2 = softplus_f(cv[2]), c3 = softplus_f(cv[3]);
    float cinv = 1.0f / (fabsf(c0) + fabsf(c1) + fabsf(c2) + fabsf(c3));
    c0 *= cinv; c1 *= cinv; c2 *= cinv; c3 *= cinv;
    float b0 = a0 * sp_adiv * L2E, b1 = a1 * sp_adiv * L2E;
    float b2 = a2 * sp_adiv * L2E, b3 = a3 * sp_adiv * L2E;
    float bmin = fminf(fminf(b0, b1), fminf(b2, b3));
    float thr  = 151.0f / bmin;   // t >= thr  =>  all exp2 terms == 0.0f

    __syncthreads();

    int stride = gridDim.x * blockDim.x;
    int tid    = blockIdx.x * blockDim.x + threadIdx.x;

    for (int e = tid; e < E; e += 2 * stride) {
        int  e2   = e + stride;
        bool has2 = (e2 < E);

        // ---- issue ALL loads for both edges first (max MLP) ----
        float rx1 = r[3 * e + 0], ry1 = r[3 * e + 1], rz1 = r[3 * e + 2];
        int   i1  = ii[e],        j1  = jj[e];

        int   e2c = has2 ? e2 : e;      // safe dummy
        float rx2 = r[3 * e2c + 0], ry2 = r[3 * e2c + 1], rz2 = r[3 * e2c + 2];
        int   i2  = ii[e2c],        j2  = jj[e2c];

        float2 a1i = g_atom2[i1];
        float2 a1j = g_atom2[j1];
        float2 a2i = g_atom2[i2];
        float2 a2j = g_atom2[j2];

        // ---- compute ----
        int m1, m2;
        float ee1 = edge_energy(rx1, ry1, rz1, a1i, a1j,
                                b0, b1, b2, b3, c0, c1, c2, c3, thr, &m1);
        float ee2 = edge_energy(rx2, ry2, rz2, a2i, a2j,
                                b0, b1, b2, b3, c0, c1, c2, c3, thr, &m2);

        if (ee1 != 0.0f)          atomicAdd(&bins[m1], ee1);
        if (has2 && ee2 != 0.0f)  atomicAdd(&bins[m2], ee2);
    }

    __syncthreads();
    for (int b = threadIdx.x; b < M; b += blockDim.x) {
        float v = bins[b];
        if (v != 0.0f) atomicAdd(&y[b], v);
    }
}

extern "C" void kernel_launch(void* const* d_in, const int* in_sizes, int n_in,
                              void* d_out, int out_size) {
    const float* Z    = (const float*)d_in[0];
    const float* r    = (const float*)d_in[1];
    const int*   ii   = (const int*)  d_in[2];
    const int*   jj   = (const int*)  d_in[3];
    const int*   im   = (const int*)  d_in[4];
    const float* adiv = (const float*)d_in[5];
    const float* apow = (const float*)d_in[6];
    const float* av   = (const float*)d_in[7];
    const float* cv   = (const float*)d_in[8];

    int N = in_sizes[0];
    int E = in_sizes[2];
    int M = out_size;
    float* y = (float*)d_out;

    int prep_n = (N > M ? N : M);
    k_atom_prep<<<(prep_n + 255) / 256, 256>>>(Z, im, apow, N, y, M);

    int grid = 148 * 8;                     // oversubscribe; grid-stride absorbs
    size_t smem = (size_t)M * sizeof(float);
    k_edge_energy<<<grid, 256, smem>>>(r, ii, jj, adiv, av, cv, E, y, M);
}

// round 3
// speedup vs baseline: 1.6290x; 1.5686x over previous
#include <cuda_runtime.h>
#include <stdint.h>

#define KEHALF  7.199822675975274f
#define CUTOFF  10.0f
#define L2E     1.4426950408889634f
#define ZMAX    94
#define LUT_REP 32

// per-atom z-index bytes (Z-1), built by prep kernel
__device__ __align__(16) uint8_t g_ztab[131072];

__device__ __forceinline__ float softplus_f(float x) {
    return (x > 20.0f) ? x : log1pf(__expf(x));
}

__global__ void k_prep(const float* __restrict__ Z, int N,
                       float* __restrict__ y, int M) {
    int i = blockIdx.x * blockDim.x + threadIdx.x;
    if (i < M) y[i] = 0.0f;
    if (i < N && i < 131072) g_ztab[i] = (uint8_t)((int)(Z[i] + 0.5f) - 1);
}

template <bool STAGED>
__global__ __launch_bounds__(1024, 1) void k_edge(
    const float* __restrict__ r,
    const int*   __restrict__ ii,
    const int*   __restrict__ jj,
    const int*   __restrict__ im,
    const float* __restrict__ adiv,
    const float* __restrict__ apow,
    const float* __restrict__ av,
    const float* __restrict__ cv,
    int N, int E, float* __restrict__ y, int M)
{
    extern __shared__ char smem_raw[];
    float*   bins = (float*)smem_raw;
    float*   zlut = bins + M;
    uint8_t* ztab = (uint8_t*)(((uintptr_t)(zlut + ZMAX * LUT_REP) + 15) & ~(uintptr_t)15);

    int tid = threadIdx.x;

    for (int b = tid; b < M; b += blockDim.x) bins[b] = 0.0f;

    // bank-replicated z-LUT: entry zi lives at zlut[zi*32 + lane] -> bank == lane
    float sp = softplus_f(apow[0]);
    for (int k = tid; k < ZMAX * LUT_REP; k += blockDim.x) {
        int zi = k / LUT_REP;
        zlut[k] = exp2f(sp * log2f((float)(zi + 1)));
    }

    if (STAGED) {
        const int4* src = (const int4*)g_ztab;
        int4*       dst = (int4*)ztab;
        int n16 = N >> 4;
        for (int k = tid; k < n16; k += blockDim.x) dst[k] = src[k];
        for (int k = (n16 << 4) + tid; k < N; k += blockDim.x) ztab[k] = g_ztab[k];
    }

    // scalar coefficients
    float sp_adiv = softplus_f(adiv[0]);
    float a0 = softplus_f(av[0]), a1 = softplus_f(av[1]);
    float a2 = softplus_f(av[2]), a3 = softplus_f(av[3]);
    float c0 = softplus_f(cv[0]), c1 = softplus_f(cv[1]);
    float c2 = softplus_f(cv[2]), c3 = softplus_f(cv[3]);
    float cinv = 1.0f / (fabsf(c0) + fabsf(c1) + fabsf(c2) + fabsf(c3));
    c0 *= cinv; c1 *= cinv; c2 *= cinv; c3 *= cinv;
    float b0 = a0 * sp_adiv * L2E, b1 = a1 * sp_adiv * L2E;
    float b2 = a2 * sp_adiv * L2E, b3 = a3 * sp_adiv * L2E;
    float bmin = fminf(fminf(b0, b1), fminf(b2, b3));
    float thr  = 151.0f / bmin;   // t >= thr => every exp2 term is exactly 0.0f

    __syncthreads();

    int lane   = tid & 31;
    int stride = gridDim.x * blockDim.x;

    for (int e = blockIdx.x * blockDim.x + tid; e < E; e += 2 * stride) {
        int  e2   = e + stride;
        bool has2 = (e2 < E);
        int  e2c  = has2 ? e2 : e;

        // ---- batch all streaming loads ----
        float rx1 = r[3 * e + 0],   ry1 = r[3 * e + 1],   rz1 = r[3 * e + 2];
        float rx2 = r[3 * e2c + 0], ry2 = r[3 * e2c + 1], rz2 = r[3 * e2c + 2];
        int i1 = ii[e],   j1 = jj[e];
        int i2 = ii[e2c], j2 = jj[e2c];

        // ---- byte gathers: smem (no L1 wavefronts) or gmem fallback ----
        int zi1, zj1, zi2, zj2;
        if (STAGED) {
            zi1 = ztab[i1]; zj1 = ztab[j1];
            zi2 = ztab[i2]; zj2 = ztab[j2];
        } else {
            zi1 = g_ztab[i1]; zj1 = g_ztab[j1];
            zi2 = g_ztab[i2]; zj2 = g_ztab[j2];
        }

        float z1 = zlut[zi1 * LUT_REP + lane] + zlut[zj1 * LUT_REP + lane];
        float z2 = zlut[zi2 * LUT_REP + lane] + zlut[zj2 * LUT_REP + lane];

        // edge 1
        {
            float s  = fmaf(rx1, rx1, fmaf(ry1, ry1, rz1 * rz1));
            float rs = rsqrtf(s);
            float d  = s * rs;
            float t  = z1 * d;
            if (t < thr && d < CUTOFF) {
                float f = c0 * exp2f(-b0 * t) + c1 * exp2f(-b1 * t)
                        + c2 * exp2f(-b2 * t) + c3 * exp2f(-b3 * t);
                float u  = d * (1.0f / CUTOFF);
                float u3 = u * u * u;
                float q  = fmaf(-6.0f, u, 15.0f);
                q        = fmaf(q, u, -10.0f);
                float fc = fmaf(u3, q, 1.0f);
                float Zi = (float)(zi1 + 1), Zj = (float)(zj1 + 1);
                float ee = KEHALF * f * fc * Zi * Zj * rs;
                if (ee != 0.0f) atomicAdd(&bins[im[i1]], ee);
            }
        }
        // edge 2
        if (has2) {
            float s  = fmaf(rx2, rx2, fmaf(ry2, ry2, rz2 * rz2));
            float rs = rsqrtf(s);
            float d  = s * rs;
            float t  = z2 * d;
            if (t < thr && d < CUTOFF) {
                float f = c0 * exp2f(-b0 * t) + c1 * exp2f(-b1 * t)
                        + c2 * exp2f(-b2 * t) + c3 * exp2f(-b3 * t);
                float u  = d * (1.0f / CUTOFF);
                float u3 = u * u * u;
                float q  = fmaf(-6.0f, u, 15.0f);
                q        = fmaf(q, u, -10.0f);
                float fc = fmaf(u3, q, 1.0f);
                float Zi = (float)(zi2 + 1), Zj = (float)(zj2 + 1);
                float ee = KEHALF * f * fc * Zi * Zj * rs;
                if (ee != 0.0f) atomicAdd(&bins[im[i2]], ee);
            }
        }
    }

    __syncthreads();
    for (int b = tid; b < M; b += blockDim.x) {
        float v = bins[b];
        if (v != 0.0f) atomicAdd(&y[b], v);
    }
}

extern "C" void kernel_launch(void* const* d_in, const int* in_sizes, int n_in,
                              void* d_out, int out_size) {
    const float* Z    = (const float*)d_in[0];
    const float* r    = (const float*)d_in[1];
    const int*   ii   = (const int*)  d_in[2];
    const int*   jj   = (const int*)  d_in[3];
    const int*   im   = (const int*)  d_in[4];
    const float* adiv = (const float*)d_in[5];
    const float* apow = (const float*)d_in[6];
    const float* av   = (const float*)d_in[7];
    const float* cv   = (const float*)d_in[8];

    int N = in_sizes[0];
    int E = in_sizes[2];
    int M = out_size;
    float* y = (float*)d_out;

    int prep_n = (N > M ? N : M);
    k_prep<<<(prep_n + 255) / 256, 256>>>(Z, N, y, M);

    int sm_count = 148;
    cudaDeviceGetAttribute(&sm_count, cudaDevAttrMultiProcessorCount, 0);

    size_t smem_fixed  = (size_t)M * 4 + (size_t)ZMAX * LUT_REP * 4 + 32;
    size_t smem_staged = smem_fixed + (size_t)N;

    if (N <= 131072 && smem_staged <= 220 * 1024) {
        cudaFuncSetAttribute(k_edge<true>,
                             cudaFuncAttributeMaxDynamicSharedMemorySize,
                             (int)smem_staged);
        k_edge<true><<<sm_count, 1024, smem_staged>>>(
            r, ii, jj, im, adiv, apow, av, cv, N, E, y, M);
    } else {
        cudaFuncSetAttribute(k_edge<false>,
                             cudaFuncAttributeMaxDynamicSharedMemorySize,
                             (int)smem_fixed);
        k_edge<false><<<sm_count, 1024, smem_fixed>>>(
            r, ii, jj, im, adiv, apow, av, cv, N, E, y, M);
    }
}

// round 4
// speedup vs baseline: 1.6314x; 1.0015x over previous
#include <cuda_runtime.h>
#include <stdint.h>

#define KEHALF  7.199822675975274f
#define CUTOFF  10.0f
#define L2E     1.4426950408889634f
#define ZMAX    94
#define LUT_REP 32
#define CHUNK   4

// per-atom z-index bytes (Z-1), built by prep kernel
__device__ __align__(16) uint8_t g_ztab[131072];

__device__ __forceinline__ float softplus_f(float x) {
    return (x > 20.0f) ? x : log1pf(__expf(x));
}

__global__ void k_prep(const float* __restrict__ Z, int N,
                       float* __restrict__ y, int M) {
    int i = blockIdx.x * blockDim.x + threadIdx.x;
    if (i < M) y[i] = 0.0f;
    if (i < N && i < 131072) g_ztab[i] = (uint8_t)((int)(Z[i] + 0.5f) - 1);
}

struct Coef {
    float b0, b1, b2, b3, c0, c1, c2, c3, thr;
};

__device__ __forceinline__ Coef make_coef(const float* adiv, const float* av,
                                          const float* cv) {
    Coef k;
    float sp_adiv = softplus_f(adiv[0]);
    float a0 = softplus_f(av[0]), a1 = softplus_f(av[1]);
    float a2 = softplus_f(av[2]), a3 = softplus_f(av[3]);
    float c0 = softplus_f(cv[0]), c1 = softplus_f(cv[1]);
    float c2 = softplus_f(cv[2]), c3 = softplus_f(cv[3]);
    float cinv = 1.0f / (fabsf(c0) + fabsf(c1) + fabsf(c2) + fabsf(c3));
    k.c0 = c0 * cinv; k.c1 = c1 * cinv; k.c2 = c2 * cinv; k.c3 = c3 * cinv;
    k.b0 = a0 * sp_adiv * L2E; k.b1 = a1 * sp_adiv * L2E;
    k.b2 = a2 * sp_adiv * L2E; k.b3 = a3 * sp_adiv * L2E;
    float bmin = fminf(fminf(k.b0, k.b1), fminf(k.b2, k.b3));
    k.thr = 151.0f / bmin;   // t >= thr => every exp2 term is exactly 0.0f
    return k;
}

__device__ __forceinline__ void do_edge(
    float rx, float ry, float rz, int zi, int zj, float zsum,
    const Coef& K, float* bins, const int* __restrict__ im, int iatom)
{
    float s  = fmaf(rx, rx, fmaf(ry, ry, rz * rz));
    float rs = rsqrtf(s);
    float d  = s * rs;
    float t  = zsum * d;
    if (t < K.thr && d < CUTOFF) {
        float f = K.c0 * exp2f(-K.b0 * t) + K.c1 * exp2f(-K.b1 * t)
                + K.c2 * exp2f(-K.b2 * t) + K.c3 * exp2f(-K.b3 * t);
        float u  = d * (1.0f / CUTOFF);
        float u3 = u * u * u;
        float q  = fmaf(-6.0f, u, 15.0f);
        q        = fmaf(q, u, -10.0f);
        float fc = fmaf(u3, q, 1.0f);
        float Zi = (float)(zi + 1), Zj = (float)(zj + 1);
        float ee = KEHALF * f * fc * Zi * Zj * rs;
        if (ee != 0.0f) atomicAdd(&bins[im[iatom]], ee);
    }
}

__global__ __launch_bounds__(1024, 1) void k_edge(
    const float* __restrict__ r,
    const int*   __restrict__ ii,
    const int*   __restrict__ jj,
    const int*   __restrict__ im,
    const float* __restrict__ adiv,
    const float* __restrict__ av,
    const float* __restrict__ cv,
    int N, int E, float* __restrict__ y, int M)
{
    extern __shared__ char smem_raw[];
    float*   bins = (float*)smem_raw;
    float*   zlut = bins + M;
    uint8_t* ztab = (uint8_t*)(((uintptr_t)(zlut + ZMAX * LUT_REP) + 15) & ~(uintptr_t)15);

    int tid = threadIdx.x;

    for (int b = tid; b < M; b += blockDim.x) bins[b] = 0.0f;

    // bank-replicated z-LUT: entry zi lives at zlut[zi*32 + lane] -> bank == lane
    float sp = softplus_f(*(const float*)adiv == 0.0f ? 0.0f : 0.0f);  // placeholder avoid
    (void)sp;
    {
        float spow = softplus_f(*(const float*)&adiv[0] * 0.0f);  // dummy; real below
        (void)spow;
    }
    float sp_pow = softplus_f( ((const float*)cv)[0] * 0.0f );  // dummy
    (void)sp_pow;

    // (real LUT fill)
    // apow passed via cv? no — fix: apow pointer is separate; see params below.
    // NOTE: apow is passed through the 'av' slot? No — see kernel_launch: we pass apow
    // via a dedicated argument 'adiv' order kept. This block replaced below.

    __syncthreads();  // placeholder; real code follows
}

// ---------------------------------------------------------------------------
// The above stub got tangled; real kernel below (k_edge2 is the one launched).
// ---------------------------------------------------------------------------

__global__ __launch_bounds__(1024, 1) void k_edge2(
    const float* __restrict__ r,
    const int*   __restrict__ ii,
    const int*   __restrict__ jj,
    const int*   __restrict__ im,
    const float* __restrict__ adiv,
    const float* __restrict__ apow,
    const float* __restrict__ av,
    const float* __restrict__ cv,
    int N, int E, float* __restrict__ y, int M)
{
    extern __shared__ char smem_raw[];
    float*   bins = (float*)smem_raw;
    float*   zlut = bins + M;
    uint8_t* ztab = (uint8_t*)(((uintptr_t)(zlut + ZMAX * LUT_REP) + 15) & ~(uintptr_t)15);

    int tid = threadIdx.x;

    for (int b = tid; b < M; b += blockDim.x) bins[b] = 0.0f;

    float spw = softplus_f(apow[0]);
    for (int k = tid; k < ZMAX * LUT_REP; k += blockDim.x) {
        int zi = k / LUT_REP;
        zlut[k] = exp2f(spw * log2f((float)(zi + 1)));
    }

    {   // stage byte table into smem
        const int4* src = (const int4*)g_ztab;
        int4*       dst = (int4*)ztab;
        int n16 = N >> 4;
        for (int k = tid; k < n16; k += blockDim.x) dst[k] = src[k];
        for (int k = (n16 << 4) + tid; k < N; k += blockDim.x) ztab[k] = g_ztab[k];
    }

    Coef K = make_coef(adiv, av, cv);

    __syncthreads();

    int lane   = tid & 31;
    int stride = gridDim.x * blockDim.x * CHUNK;
    int E4     = E & ~(CHUNK - 1);
    const float4* rv = (const float4*)r;

    for (int e0 = (blockIdx.x * blockDim.x + tid) * CHUNK; e0 < E4; e0 += stride) {
        // ---- wide streaming loads: 3x LDG.128 (r) + 2x LDG.128 (indices) ----
        int   fi = (e0 >> 2) * 3;
        float4 p0 = rv[fi + 0];
        float4 p1 = rv[fi + 1];
        float4 p2 = rv[fi + 2];
        int4  iv = *(const int4*)(ii + e0);
        int4  jv = *(const int4*)(jj + e0);

        int ia[CHUNK] = {iv.x, iv.y, iv.z, iv.w};
        int ja[CHUNK] = {jv.x, jv.y, jv.z, jv.w};
        float fx[12]  = {p0.x, p0.y, p0.z, p0.w,
                         p1.x, p1.y, p1.z, p1.w,
                         p2.x, p2.y, p2.z, p2.w};

        // ---- batched smem byte gathers ----
        int zi[CHUNK], zj[CHUNK];
        #pragma unroll
        for (int k = 0; k < CHUNK; k++) {
            zi[k] = ztab[ia[k]];
            zj[k] = ztab[ja[k]];
        }
        float zs[CHUNK];
        #pragma unroll
        for (int k = 0; k < CHUNK; k++) {
            zs[k] = zlut[zi[k] * LUT_REP + lane] + zlut[zj[k] * LUT_REP + lane];
        }

        #pragma unroll
        for (int k = 0; k < CHUNK; k++) {
            do_edge(fx[3 * k], fx[3 * k + 1], fx[3 * k + 2],
                    zi[k], zj[k], zs[k], K, bins, im, ia[k]);
        }
    }

    // scalar tail
    if (blockIdx.x == 0) {
        for (int e = E4 + tid; e < E; e += blockDim.x) {
            int i = ii[e], j = jj[e];
            int zi = ztab[i], zj = ztab[j];
            float zsum = zlut[zi * LUT_REP + lane] + zlut[zj * LUT_REP + lane];
            do_edge(r[3 * e], r[3 * e + 1], r[3 * e + 2],
                    zi, zj, zsum, K, bins, im, i);
        }
    }

    __syncthreads();
    for (int b = tid; b < M; b += blockDim.x) {
        float v = bins[b];
        if (v != 0.0f) atomicAdd(&y[b], v);
    }
}

extern "C" void kernel_launch(void* const* d_in, const int* in_sizes, int n_in,
                              void* d_out, int out_size) {
    const float* Z    = (const float*)d_in[0];
    const float* r    = (const float*)d_in[1];
    const int*   ii   = (const int*)  d_in[2];
    const int*   jj   = (const int*)  d_in[3];
    const int*   im   = (const int*)  d_in[4];
    const float* adiv = (const float*)d_in[5];
    const float* apow = (const float*)d_in[6];
    const float* av   = (const float*)d_in[7];
    const float* cv   = (const float*)d_in[8];

    int N = in_sizes[0];
    int E = in_sizes[2];
    int M = out_size;
    float* y = (float*)d_out;

    int prep_n = (N > M ? N : M);
    k_prep<<<(prep_n + 255) / 256, 256>>>(Z, N, y, M);

    int sm_count = 148;
    cudaDeviceGetAttribute(&sm_count, cudaDevAttrMultiProcessorCount, 0);

    size_t smem = (size_t)M * 4 + (size_t)ZMAX * LUT_REP * 4 + 32 + (size_t)N;
    cudaFuncSetAttribute(k_edge2,
                         cudaFuncAttributeMaxDynamicSharedMemorySize, (int)smem);
    k_edge2<<<sm_count, 1024, smem>>>(
        r, ii, jj, im, adiv, apow, av, cv, N, E, y, M);
}

// round 5
// speedup vs baseline: 1.6489x; 1.0107x over previous
#include <cuda_runtime.h>
#include <stdint.h>

#define KEHALF   7.199822675975274f
#define CUTOFF   10.0f
#define L2E      1.4426950408889634f
#define ZMAX     94
#define LUT_REP  32
#define CHUNK    4
#define NTHREADS 1024

// per-atom z-index bytes (Z-1), built by prep kernel
__device__ __align__(16) uint8_t g_ztab[131072];

__device__ __forceinline__ float softplus_f(float x) {
    return (x > 20.0f) ? x : log1pf(__expf(x));
}

__global__ void k_prep(const float* __restrict__ Z, int N,
                       float* __restrict__ y, int M) {
    int i = blockIdx.x * blockDim.x + threadIdx.x;
    if (i < M) y[i] = 0.0f;
    if (i < N && i < 131072) g_ztab[i] = (uint8_t)((int)(Z[i] + 0.5f) - 1);
}

struct Chunk {
    float4 p0, p1, p2;   // 12 floats = 4 edges x (rx,ry,rz)
    int4   iv, jv;
};

__device__ __forceinline__ Chunk load_chunk(const float4* __restrict__ rv,
                                            const int* __restrict__ ii,
                                            const int* __restrict__ jj,
                                            int e0) {
    Chunk c;
    int fi = (e0 >> 2) * 3;
    c.p0 = __ldcs(rv + fi + 0);
    c.p1 = __ldcs(rv + fi + 1);
    c.p2 = __ldcs(rv + fi + 2);
    c.iv = __ldcs((const int4*)(ii + e0));
    c.jv = __ldcs((const int4*)(jj + e0));
    return c;
}

// coefficients live in smem: cf[0..3]=b0..b3, cf[4..7]=c0..c7, cf[8]=thr
__device__ __forceinline__ void do_edge(
    float rx, float ry, float rz, int zi, int zj, float zsum,
    float thr, const float* __restrict__ cf,
    float* bins, const int* __restrict__ im, int iatom)
{
    float s  = fmaf(rx, rx, fmaf(ry, ry, rz * rz));
    float rs = rsqrtf(s);
    float d  = s * rs;
    float t  = zsum * d;
    if (t < thr && d < CUTOFF) {                    // ~1% of edges
        float f = cf[4] * exp2f(-cf[0] * t) + cf[5] * exp2f(-cf[1] * t)
                + cf[6] * exp2f(-cf[2] * t) + cf[7] * exp2f(-cf[3] * t);
        float u  = d * (1.0f / CUTOFF);
        float u3 = u * u * u;
        float q  = fmaf(-6.0f, u, 15.0f);
        q        = fmaf(q, u, -10.0f);
        float fc = fmaf(u3, q, 1.0f);
        float Zi = (float)(zi + 1), Zj = (float)(zj + 1);
        float ee = KEHALF * f * fc * Zi * Zj * rs;
        if (ee != 0.0f) atomicAdd(&bins[im[iatom]], ee);
    }
}

__device__ __forceinline__ void process_chunk(
    const Chunk& c, const uint8_t* __restrict__ ztab,
    const float* __restrict__ zlut, float thr, const float* __restrict__ cf,
    float* bins, const int* __restrict__ im, int lane)
{
    int ia[CHUNK] = {c.iv.x, c.iv.y, c.iv.z, c.iv.w};
    int ja[CHUNK] = {c.jv.x, c.jv.y, c.jv.z, c.jv.w};
    float fx[12]  = {c.p0.x, c.p0.y, c.p0.z, c.p0.w,
                     c.p1.x, c.p1.y, c.p1.z, c.p1.w,
                     c.p2.x, c.p2.y, c.p2.z, c.p2.w};

    int zi[CHUNK], zj[CHUNK];
    #pragma unroll
    for (int k = 0; k < CHUNK; k++) {
        zi[k] = ztab[ia[k]];
        zj[k] = ztab[ja[k]];
    }
    float zs[CHUNK];
    #pragma unroll
    for (int k = 0; k < CHUNK; k++)
        zs[k] = zlut[zi[k] * LUT_REP + lane] + zlut[zj[k] * LUT_REP + lane];

    #pragma unroll
    for (int k = 0; k < CHUNK; k++)
        do_edge(fx[3 * k], fx[3 * k + 1], fx[3 * k + 2],
                zi[k], zj[k], zs[k], thr, cf, bins, im, ia[k]);
}

__global__ __launch_bounds__(NTHREADS, 1) void k_edge(
    const float* __restrict__ r,
    const int*   __restrict__ ii,
    const int*   __restrict__ jj,
    const int*   __restrict__ im,
    const float* __restrict__ adiv,
    const float* __restrict__ apow,
    const float* __restrict__ av,
    const float* __restrict__ cv,
    int N, int E, float* __restrict__ y, int M)
{
    extern __shared__ char smem_raw[];
    float*   bins = (float*)smem_raw;
    float*   cf   = bins + M;                 // 16 floats (coef block)
    float*   zlut = cf + 16;
    uint8_t* ztab = (uint8_t*)(((uintptr_t)(zlut + ZMAX * LUT_REP) + 15) & ~(uintptr_t)15);

    int tid  = threadIdx.x;
    int lane = tid & 31;

    for (int b = tid; b < M; b += blockDim.x) bins[b] = 0.0f;

    // one thread computes coefficients into smem
    if (tid == 0) {
        float sp_adiv = softplus_f(adiv[0]);
        float a0 = softplus_f(av[0]), a1 = softplus_f(av[1]);
        float a2 = softplus_f(av[2]), a3 = softplus_f(av[3]);
        float c0 = softplus_f(cv[0]), c1 = softplus_f(cv[1]);
        float c2 = softplus_f(cv[2]), c3 = softplus_f(cv[3]);
        float cinv = 1.0f / (fabsf(c0) + fabsf(c1) + fabsf(c2) + fabsf(c3));
        float b0 = a0 * sp_adiv * L2E, b1 = a1 * sp_adiv * L2E;
        float b2 = a2 * sp_adiv * L2E, b3 = a3 * sp_adiv * L2E;
        cf[0] = b0; cf[1] = b1; cf[2] = b2; cf[3] = b3;
        cf[4] = c0 * cinv; cf[5] = c1 * cinv; cf[6] = c2 * cinv; cf[7] = c3 * cinv;
        float bmin = fminf(fminf(b0, b1), fminf(b2, b3));
        cf[8] = 151.0f / bmin;   // t >= thr => every exp2 term is exactly 0.0f
    }

    // bank-replicated z-LUT: zlut[zi*32 + lane] -> bank == lane, conflict-free
    {
        float spw = softplus_f(apow[0]);
        for (int k = tid; k < ZMAX * LUT_REP; k += blockDim.x) {
            int zi = k / LUT_REP;
            zlut[k] = exp2f(spw * log2f((float)(zi + 1)));
        }
    }

    {   // stage byte table into smem
        const int4* src = (const int4*)g_ztab;
        int4*       dst = (int4*)ztab;
        int n16 = N >> 4;
        for (int k = tid; k < n16; k += blockDim.x) dst[k] = src[k];
        for (int k = (n16 << 4) + tid; k < N; k += blockDim.x) ztab[k] = g_ztab[k];
    }

    __syncthreads();

    float thr = cf[8];

    int stride = gridDim.x * blockDim.x * CHUNK;
    int E4     = E & ~(CHUNK - 1);
    const float4* rv = (const float4*)r;

    int e = (blockIdx.x * blockDim.x + tid) * CHUNK;

    // ---- 2-deep software pipeline over chunk iterations ----
    if (e < E4) {
        Chunk cur = load_chunk(rv, ii, jj, e);
        while (true) {
            int  en   = e + stride;
            bool hasn = (en < E4);
            Chunk nxt;
            if (hasn) nxt = load_chunk(rv, ii, jj, en);   // in flight during compute
            process_chunk(cur, ztab, zlut, thr, cf, bins, im, lane);
            if (!hasn) break;
            cur = nxt;
            e   = en;
        }
    }

    // scalar tail (E not multiple of CHUNK)
    if (blockIdx.x == 0) {
        for (int t = E4 + tid; t < E; t += blockDim.x) {
            int i = ii[t], j = jj[t];
            int zi = ztab[i], zj = ztab[j];
            float zsum = zlut[zi * LUT_REP + lane] + zlut[zj * LUT_REP + lane];
            do_edge(r[3 * t], r[3 * t + 1], r[3 * t + 2],
                    zi, zj, zsum, thr, cf, bins, im, i);
        }
    }

    __syncthreads();
    for (int b = tid; b < M; b += blockDim.x) {
        float v = bins[b];
        if (v != 0.0f) atomicAdd(&y[b], v);
    }
}

extern "C" void kernel_launch(void* const* d_in, const int* in_sizes, int n_in,
                              void* d_out, int out_size) {
    const float* Z    = (const float*)d_in[0];
    const float* r    = (const float*)d_in[1];
    const int*   ii   = (const int*)  d_in[2];
    const int*   jj   = (const int*)  d_in[3];
    const int*   im   = (const int*)  d_in[4];
    const float* adiv = (const float*)d_in[5];
    const float* apow = (const float*)d_in[6];
    const float* av   = (const float*)d_in[7];
    const float* cv   = (const float*)d_in[8];

    int N = in_sizes[0];
    int E = in_sizes[2];
    int M = out_size;
    float* y = (float*)d_out;

    int prep_n = (N > M ? N : M);
    k_prep<<<(prep_n + 255) / 256, 256>>>(Z, N, y, M);

    int sm_count = 148;
    cudaDeviceGetAttribute(&sm_count, cudaDevAttrMultiProcessorCount, 0);

    size_t smem = (size_t)M * 4 + 16 * 4 + (size_t)ZMAX * LUT_REP * 4 + 32 + (size_t)N;
    cudaFuncSetAttribute(k_edge,
                         cudaFuncAttributeMaxDynamicSharedMemorySize, (int)smem);
    k_edge<<<sm_count, NTHREADS, smem>>>(
        r, ii, jj, im, adiv, apow, av, cv, N, E, y, M);
}